// round 12
// baseline (speedup 1.0000x reference)
#include <cuda_runtime.h>

#define NC 4096
#define NA 2048
#define NB (NC + NA)          // 6144 bodies
#define TPB 128
#define ITILES (NB / TPB)     // 48 i-tiles (0..31 circle, 32..47 aabb)
#define CHUNK 128             // j-chunk size
#define NCY (NC / CHUNK)      // 32 circle j-chunks
#define NAY (NA / CHUNK)      // 16 aabb j-chunks
#define NJY (NCY + NAY)       // 48 j-chunks
#define EPSF 1e-9f

// partial corrections: [NJY][NB] float2
__device__ float2 g_partial[NJY * NB];
__device__ int    g_cnt[ITILES] = {};

__device__ __forceinline__ float rsq_approx(float x) {
    float r;
    asm("rsqrt.approx.f32 %0, %1;" : "=f"(r) : "f"(x));
    return r;
}

__global__ void __launch_bounds__(TPB)
collide_kernel(const float* __restrict__ cpos, const float* __restrict__ crad,
               const float* __restrict__ apos, const float* __restrict__ ahalf,
               float* __restrict__ out)
{
    // one float4 per j-body: circle (−x, −y, 0.5*r, 0) ; aabb (−x, −y, hx, hy)
    __shared__ float4 sj[CHUNK];
    __shared__ int s_old;

    const int tid = threadIdx.x;
    const int bx  = blockIdx.x;                 // i-tile
    const int i   = bx * TPB + tid;             // body index 0..NB-1
    const bool i_is_circle = (i < NC);
    const int jy = blockIdx.y;
    const bool j_is_circle = (jy < NCY);
    const int j0 = j_is_circle ? (jy * CHUNK) : ((jy - NCY) * CHUNK);

    // stage CHUNK j-bodies (one per thread), positions negated
    {
        if (j_is_circle) {
            float2 p = ((const float2*)cpos)[j0 + tid];
            sj[tid] = make_float4(-p.x, -p.y, 0.5f * crad[j0 + tid], 0.0f);
        } else {
            float2 p = ((const float2*)apos)[j0 + tid];
            float2 h = ((const float2*)ahalf)[j0 + tid];
            sj[tid] = make_float4(-p.x, -p.y, h.x, h.y);
        }
    }

    // hoisted i-state
    float pix, piy, ra, rb;      // circle: ra=0.5*r ; aabb: ra=hx, rb=hy
    int ia = 0;
    if (i_is_circle) {
        float2 p = ((const float2*)cpos)[i];
        pix = p.x; piy = p.y;
        ra = 0.5f * crad[i]; rb = 0.0f;
    } else {
        ia = i - NC;
        float2 p = ((const float2*)apos)[ia];
        float2 h = ((const float2*)ahalf)[ia];
        pix = p.x; piy = p.y;
        ra = h.x; rb = h.y;
    }
    const float nra = -ra, nrb = -rb;   // hoisted negations for clamp

    __syncthreads();

    float cx = 0.0f, cy = 0.0f;

    if (i_is_circle) {
        if (j_is_circle) {
            // circle vs circle. EPS clamp => self-pair d=(+0,+0) contributes 0.
            #pragma unroll 8
            for (int k = 0; k < CHUNK; k++) {
                float4 b = sj[k];
                float dx = pix + b.x;                 // pi - pj (b negated)
                float dy = piy + b.y;
                float d2 = fmaxf(fmaf(dx, dx, dy * dy), EPSF);
                float inv = rsq_approx(d2);
                float s = fmaxf(fmaf(ra + b.z, inv, -0.5f), 0.0f);
                cx = fmaf(s, dx, cx);
                cy = fmaf(s, dy, cy);
            }
        } else {
            // circle vs aabb (push on circle)
            #pragma unroll 8
            for (int k = 0; k < CHUNK; k++) {
                float4 b = sj[k];
                float rx = pix + b.x;                 // ci - aj
                float ry = piy + b.y;
                float dx = rx - fminf(fmaxf(rx, -b.z), b.z);
                float dy = ry - fminf(fmaxf(ry, -b.w), b.w);
                float dd2 = fmaxf(fmaf(dx, dx, dy * dy), EPSF);
                float inv = rsq_approx(dd2);
                float s = fmaxf(fmaf(ra, inv, -0.5f), 0.0f);   // ra = 0.5*ri
                cx = fmaf(s, dx, cx);
                cy = fmaf(s, dy, cy);
            }
        }
    } else {
        if (j_is_circle) {
            // aabb vs circle: rel' = ai - cj = -rel => box push = +s*diff'
            #pragma unroll 8
            for (int k = 0; k < CHUNK; k++) {
                float4 b = sj[k];
                float rx = pix + b.x;                 // ai - cj
                float ry = piy + b.y;
                float dx = rx - fminf(fmaxf(rx, nra), ra);    // ra=hx
                float dy = ry - fminf(fmaxf(ry, nrb), rb);    // rb=hy
                float dd2 = fmaxf(fmaf(dx, dx, dy * dy), EPSF);
                float inv = rsq_approx(dd2);
                float s = fmaxf(fmaf(b.z, inv, -0.5f), 0.0f); // b.z = 0.5*rj
                cx = fmaf(s, dx, cx);
                cy = fmaf(s, dy, cy);
            }
        } else {
            // aabb vs aabb — diagonal tile needs the self-pair guard, others don't
            const bool diag = (bx - NC / TPB) * TPB == (jy - NCY) * CHUNK
                              || ((bx - NC / TPB) * TPB == (jy - NCY) * CHUNK + 0);
            if ((jy - NCY) * CHUNK <= ia && ia < (jy - NCY) * CHUNK + CHUNK) {
                // diagonal: guard ia != j
                #pragma unroll 8
                for (int k = 0; k < CHUNK; k++) {
                    float4 b = sj[k];
                    int j = j0 + k;
                    float dax = pix + b.x;
                    float day = piy + b.y;
                    float ovx = (ra + b.z) - fabsf(dax);
                    float ovy = (rb + b.w) - fabsf(day);
                    bool hit = (ovx > 0.0f) && (ovy > 0.0f) && (ia != j);
                    bool usex = (ovx <= ovy);
                    cx += (hit && usex)  ? copysignf(0.5f * ovx, dax) : 0.0f;
                    cy += (hit && !usex) ? copysignf(0.5f * ovy, day) : 0.0f;
                }
            } else {
                #pragma unroll 8
                for (int k = 0; k < CHUNK; k++) {
                    float4 b = sj[k];
                    float dax = pix + b.x;
                    float day = piy + b.y;
                    float ovx = (ra + b.z) - fabsf(dax);
                    float ovy = (rb + b.w) - fabsf(day);
                    bool hit = (ovx > 0.0f) && (ovy > 0.0f);
                    bool usex = (ovx <= ovy);
                    cx += (hit && usex)  ? copysignf(0.5f * ovx, dax) : 0.0f;
                    cy += (hit && !usex) ? copysignf(0.5f * ovy, day) : 0.0f;
                }
            }
        }
    }

    g_partial[(size_t)jy * NB + i] = make_float2(cx, cy);

    // ---- last-arriving block of this i-tile folds all partials (fixed order) ----
    __threadfence();                       // release partial write
    if (tid == 0) s_old = atomicAdd(&g_cnt[bx], 1);
    __syncthreads();
    if (s_old == NJY - 1) {
        __threadfence();                   // see all partials
        float2 base = i_is_circle ? ((const float2*)cpos)[i]
                                  : ((const float2*)apos)[i - NC];
        float sx = base.x, sy = base.y;
        #pragma unroll
        for (int y = 0; y < NJY; y++) {    // fixed order => deterministic
            float2 p = g_partial[(size_t)y * NB + i];
            sx += p.x; sy += p.y;
        }
        ((float2*)out)[i] = make_float2(sx, sy);
        if (tid == 0) g_cnt[bx] = 0;       // reset for next graph replay
    }
}

extern "C" void kernel_launch(void* const* d_in, const int* in_sizes, int n_in,
                              void* d_out, int out_size)
{
    const float* cpos  = (const float*)d_in[0];   // [4096,2]
    const float* crad  = (const float*)d_in[1];   // [4096]
    const float* apos  = (const float*)d_in[2];   // [2048,2]
    const float* ahalf = (const float*)d_in[3];   // [2048,2]
    float* out = (float*)d_out;                   // [6144,2]

    dim3 grid(ITILES, NJY);
    collide_kernel<<<grid, TPB>>>(cpos, crad, apos, ahalf, out);
}

// round 13
// speedup vs baseline: 1.0790x; 1.0790x over previous
#include <cuda_runtime.h>

#define NC 4096
#define NA 2048
#define NB (NC + NA)          // 6144 bodies
#define TPB 128
#define TILE 128
#define NT (NB / TILE)        // 48 tiles: 0..31 circle, 32..47 aabb
#define NCT (NC / TILE)       // 32
#define NPAIRS (NT * (NT + 1) / 2)   // 1176
#define EPSF 1e-9f

// partial corrections: slice y = "other tile" -> [NT][NB] float2
__device__ float2 g_partial[NT * NB];
__device__ int    g_cnt[NT] = {};

__device__ __forceinline__ float rsq_approx(float x) {
    float r;
    asm("rsqrt.approx.f32 %0, %1;" : "=f"(r) : "f"(x));
    return r;
}
__device__ __forceinline__ float bfly_sum(float v) {
    #pragma unroll
    for (int m = 16; m > 0; m >>= 1)
        v += __shfl_xor_sync(0xffffffffu, v, m);
    return v;
}

__global__ void __launch_bounds__(TPB)
collide_kernel(const float* __restrict__ cpos, const float* __restrict__ crad,
               const float* __restrict__ apos, const float* __restrict__ ahalf,
               float* __restrict__ out)
{
    // j-tile: circle (−x, −y, r, 0) ; aabb (−x, −y, hx, hy)
    __shared__ float4 sj[TILE];
    __shared__ float2 accA[4][TILE];   // per-warp i-side partials
    __shared__ int s_oldA, s_oldB;

    const int tid = threadIdx.x;
    const int w   = tid >> 5;
    const int ln  = tid & 31;

    // decode unordered tile pair (bi <= bj) from block id
    int p = blockIdx.x, bi = 0;
    while (p >= NT - bi) { p -= NT - bi; bi++; }
    const int bj = bi + p;
    const bool icirc = (bi < NCT);
    const bool jcirc = (bj < NCT);
    const bool diag  = (bi == bj);

    // stage j-tile (positions negated)
    {
        if (jcirc) {
            int j = bj * TILE + tid;
            float2 q = ((const float2*)cpos)[j];
            sj[tid] = make_float4(-q.x, -q.y, crad[j], 0.0f);
        } else {
            int j = bj * TILE + tid - NC;
            float2 q = ((const float2*)apos)[j];
            float2 h = ((const float2*)ahalf)[j];
            sj[tid] = make_float4(-q.x, -q.y, h.x, h.y);
        }
    }

    // i-state: 4 bodies per lane (local index m*32+ln)
    float pix[4], piy[4], ra4[4], rb4[4];
    #pragma unroll
    for (int m = 0; m < 4; m++) {
        int il = m * 32 + ln;
        if (icirc) {
            int i = bi * TILE + il;
            float2 q = ((const float2*)cpos)[i];
            pix[m] = q.x; piy[m] = q.y;
            ra4[m] = 0.5f * crad[i]; rb4[m] = 0.0f;
        } else {
            int i = bi * TILE + il - NC;
            float2 q = ((const float2*)apos)[i];
            float2 h = ((const float2*)ahalf)[i];
            pix[m] = q.x; piy[m] = q.y;
            ra4[m] = h.x; rb4[m] = h.y;
        }
    }
    __syncthreads();

    float cx[4] = {0,0,0,0}, cy[4] = {0,0,0,0};
    float jrx = 0.0f, jry = 0.0f;
    const int jq = w * 32;               // this warp's j-quarter (local base)

    if (!diag) {
        if (icirc && jcirc) {
            // ---- circle vs circle, symmetric ----
            #pragma unroll 4
            for (int jj = 0; jj < 32; jj++) {
                float4 b = sj[jq + jj];
                float pxs = 0.0f, pys = 0.0f;
                #pragma unroll
                for (int m = 0; m < 4; m++) {
                    float dx = pix[m] + b.x;
                    float dy = piy[m] + b.y;
                    float d2 = fmaxf(fmaf(dx, dx, dy * dy), EPSF);
                    float inv = rsq_approx(d2);
                    float hs = fmaf(0.5f, b.z, ra4[m]);     // 0.5*(ri+rj)
                    float s = fmaxf(fmaf(hs, inv, -0.5f), 0.0f);
                    float px = s * dx, py = s * dy;
                    cx[m] += px; cy[m] += py;
                    pxs += px;   pys += py;
                }
                pxs = bfly_sum(pxs); pys = bfly_sum(pys);
                if (ln == jj) { jrx -= pxs; jry -= pys; }   // Newton's 3rd law
            }
        } else if (icirc && !jcirc) {
            // ---- circle(i) vs aabb(j), symmetric ----
            #pragma unroll 4
            for (int jj = 0; jj < 32; jj++) {
                float4 b = sj[jq + jj];
                float pxs = 0.0f, pys = 0.0f;
                #pragma unroll
                for (int m = 0; m < 4; m++) {
                    float rx = pix[m] + b.x;                // ci - aj
                    float ry = piy[m] + b.y;
                    float dx = rx - fminf(fmaxf(rx, -b.z), b.z);
                    float dy = ry - fminf(fmaxf(ry, -b.w), b.w);
                    float dd2 = fmaxf(fmaf(dx, dx, dy * dy), EPSF);
                    float inv = rsq_approx(dd2);
                    float s = fmaxf(fmaf(ra4[m], inv, -0.5f), 0.0f);  // ra=0.5*ri
                    float px = s * dx, py = s * dy;
                    cx[m] += px; cy[m] += py;               // push on circle
                    pxs += px;   pys += py;
                }
                pxs = bfly_sum(pxs); pys = bfly_sum(pys);
                if (ln == jj) { jrx -= pxs; jry -= pys; }   // opposite on box
            }
        } else {
            // ---- aabb vs aabb, symmetric ----
            #pragma unroll 4
            for (int jj = 0; jj < 32; jj++) {
                float4 b = sj[jq + jj];
                float pxs = 0.0f, pys = 0.0f;
                #pragma unroll
                for (int m = 0; m < 4; m++) {
                    float dax = pix[m] + b.x;
                    float day = piy[m] + b.y;
                    float ovx = (ra4[m] + b.z) - fabsf(dax);
                    float ovy = (rb4[m] + b.w) - fabsf(day);
                    bool hit = (ovx > 0.0f) && (ovy > 0.0f);
                    bool ux  = (ovx <= ovy);
                    float px = (hit && ux)  ? copysignf(0.5f * ovx, dax) : 0.0f;
                    float py = (hit && !ux) ? copysignf(0.5f * ovy, day) : 0.0f;
                    cx[m] += px; cy[m] += py;
                    pxs += px;   pys += py;
                }
                pxs = bfly_sum(pxs); pys = bfly_sum(pys);
                if (ln == jj) { jrx -= pxs; jry -= pys; }
            }
        }
    } else {
        // ---- diagonal tile: one-sided over this warp's j-quarter ----
        if (icirc) {
            // cc diag: EPS clamp makes the self-pair contribute exactly 0
            #pragma unroll 4
            for (int jj = 0; jj < 32; jj++) {
                float4 b = sj[jq + jj];
                #pragma unroll
                for (int m = 0; m < 4; m++) {
                    float dx = pix[m] + b.x;
                    float dy = piy[m] + b.y;
                    float d2 = fmaxf(fmaf(dx, dx, dy * dy), EPSF);
                    float inv = rsq_approx(d2);
                    float hs = fmaf(0.5f, b.z, ra4[m]);
                    float s = fmaxf(fmaf(hs, inv, -0.5f), 0.0f);
                    cx[m] = fmaf(s, dx, cx[m]);
                    cy[m] = fmaf(s, dy, cy[m]);
                }
            }
        } else {
            // aa diag: guard self-pair (local index compare)
            #pragma unroll 4
            for (int jj = 0; jj < 32; jj++) {
                float4 b = sj[jq + jj];
                int jl = jq + jj;
                #pragma unroll
                for (int m = 0; m < 4; m++) {
                    int il = m * 32 + ln;
                    float dax = pix[m] + b.x;
                    float day = piy[m] + b.y;
                    float ovx = (ra4[m] + b.z) - fabsf(dax);
                    float ovy = (rb4[m] + b.w) - fabsf(day);
                    bool hit = (ovx > 0.0f) && (ovy > 0.0f) && (il != jl);
                    bool ux  = (ovx <= ovy);
                    cx[m] += (hit && ux)  ? copysignf(0.5f * ovx, dax) : 0.0f;
                    cy[m] += (hit && !ux) ? copysignf(0.5f * ovy, day) : 0.0f;
                }
            }
        }
    }

    // ---- i-side: merge the 4 warps' partial sums (fixed order) ----
    #pragma unroll
    for (int m = 0; m < 4; m++)
        accA[w][m * 32 + ln] = make_float2(cx[m], cy[m]);
    __syncthreads();
    {
        float2 a0 = accA[0][tid], a1 = accA[1][tid];
        float2 a2 = accA[2][tid], a3 = accA[3][tid];
        float sx = ((a0.x + a1.x) + a2.x) + a3.x;
        float sy = ((a0.y + a1.y) + a2.y) + a3.y;
        g_partial[(size_t)bj * NB + bi * TILE + tid] = make_float2(sx, sy);
    }
    // ---- j-side: each warp owns its quarter, write directly ----
    if (!diag)
        g_partial[(size_t)bi * NB + bj * TILE + jq + ln] = make_float2(jrx, jry);

    // ---- counters + fold by last-arriving block per tile ----
    __threadfence();                       // release all our partial writes
    __syncthreads();
    if (tid == 0) {
        s_oldA = atomicAdd(&g_cnt[bi], 1);
        s_oldB = diag ? -2 : atomicAdd(&g_cnt[bj], 1);
    }
    __syncthreads();

    #pragma unroll
    for (int which = 0; which < 2; which++) {
        int old = (which == 0) ? s_oldA : s_oldB;
        int T   = (which == 0) ? bi : bj;
        if (old == NT - 1) {
            __threadfence();               // acquire: see all 48 slices
            int idx = T * TILE + tid;
            float2 base = (idx < NC) ? ((const float2*)cpos)[idx]
                                     : ((const float2*)apos)[idx - NC];
            float sx = base.x, sy = base.y;
            #pragma unroll 8
            for (int y = 0; y < NT; y++) { // fixed order => deterministic
                float2 v = g_partial[(size_t)y * NB + idx];
                sx += v.x; sy += v.y;
            }
            ((float2*)out)[idx] = make_float2(sx, sy);
            if (tid == 0) g_cnt[T] = 0;    // reset for next graph replay
        }
    }
}

extern "C" void kernel_launch(void* const* d_in, const int* in_sizes, int n_in,
                              void* d_out, int out_size)
{
    const float* cpos  = (const float*)d_in[0];   // [4096,2]
    const float* crad  = (const float*)d_in[1];   // [4096]
    const float* apos  = (const float*)d_in[2];   // [2048,2]
    const float* ahalf = (const float*)d_in[3];   // [2048,2]
    float* out = (float*)d_out;                   // [6144,2]

    collide_kernel<<<NPAIRS, TPB>>>(cpos, crad, apos, ahalf, out);
}